// round 1
// baseline (speedup 1.0000x reference)
#include <cuda_runtime.h>
#include <math.h>

#define Bq   8
#define Nseq 512
#define Edim 256
#define Hh   8
#define DKd  32
#define NEGV (-1e10f)
#define SCALE 0.17677669529663687f   // 1/sqrt(32)

// ---------------- scratch (device globals; no allocs allowed) ----------------
__device__ float g_q[Bq*Hh*Nseq*DKd];        // (B,H,N,DK)
__device__ float g_k[Bq*Hh*Nseq*DKd];
__device__ float g_v[Bq*Hh*Nseq*DKd];
__device__ float g_obar[3*Bq*Nseq*Edim];     // per-bar attention outputs, (bar,B,N,E)
__device__ float g_x[Bq*Nseq*3*Edim];        // concat buffer (B,N,768)
__device__ float g_h1[Bq*Nseq*Edim];         // relu(x@Ws1+bs1)

// ---------------- generic tiled fp32 GEMM: C = act(A@W + bias) ---------------
// A: MxK row-major; W: KxNcol (row stride ldw); output 64x64 tile per block.
// headsplit: write C[((b*H+h)*N+n)*DK+d] instead of C[m*ldc+col].
__global__ __launch_bounds__(256) void gemm_kernel(
    const float* __restrict__ A, const float* __restrict__ W,
    const float* __restrict__ bias, float* __restrict__ C,
    int M, int Kd, int ldw, int ldc, int do_relu, int headsplit)
{
    __shared__ float As[64][20];   // 64x16 A tile (padded, 16B-aligned rows)
    __shared__ float Ws[16][68];   // 16x64 W tile

    const int m0 = blockIdx.x << 6;
    const int n0 = blockIdx.y << 6;
    const int tid = threadIdx.x;
    const int tx = tid & 15, ty = tid >> 4;

    float acc[4][4] = {};

    for (int k0 = 0; k0 < Kd; k0 += 16) {
        {   // A tile: thread -> row tid/4, 4 cols
            int r = tid >> 2;
            int c = (tid & 3) << 2;
            float4 v = *(const float4*)&A[(size_t)(m0 + r) * Kd + k0 + c];
            *(float4*)&As[r][c] = v;
        }
        {   // W tile: thread -> row tid/16, 4 cols
            int r = tid >> 4;
            int c = (tid & 15) << 2;
            float4 v = *(const float4*)&W[(size_t)(k0 + r) * ldw + n0 + c];
            *(float4*)&Ws[r][c] = v;
        }
        __syncthreads();

        #pragma unroll
        for (int kk = 0; kk < 16; kk++) {
            float a[4];
            #pragma unroll
            for (int i = 0; i < 4; i++) a[i] = As[ty*4 + i][kk];
            float4 w4 = *(const float4*)&Ws[kk][tx << 2];
            float w[4] = {w4.x, w4.y, w4.z, w4.w};
            #pragma unroll
            for (int i = 0; i < 4; i++)
                #pragma unroll
                for (int j = 0; j < 4; j++)
                    acc[i][j] = fmaf(a[i], w[j], acc[i][j]);
        }
        __syncthreads();
    }

    const int col0 = n0 + (tx << 2);
    #pragma unroll
    for (int i = 0; i < 4; i++) {
        int m = m0 + ty*4 + i;
        float4 r;
        float* rp = &r.x;
        #pragma unroll
        for (int j = 0; j < 4; j++) {
            float v = acc[i][j] + bias[col0 + j];
            if (do_relu) v = fmaxf(v, 0.f);
            rp[j] = v;
        }
        if (headsplit) {
            int b = m >> 9, n = m & 511;
            int h = col0 >> 5, d = col0 & 31;
            *(float4*)&C[(((size_t)(b*Hh + h))*Nseq + n)*DKd + d] = r;
        } else {
            *(float4*)&C[(size_t)m * ldc + col0] = r;
        }
    }
}

// ---------------- fused multi-bar attention ----------------------------------
// One CTA: (b, h, 64 q rows). 3 distance bars share one exp per score element.
// No max-subtraction needed: |scores| << 1 and masked -> exp(-1e10) = 0 exactly.
__global__ __launch_bounds__(256) void attn_kernel(
    const float* __restrict__ Q, const float* __restrict__ K, const float* __restrict__ V,
    const float* __restrict__ dist, const int* __restrict__ mask,
    const float* __restrict__ cw1, const float* __restrict__ cb1,
    const float* __restrict__ cw2, const float* __restrict__ cb2,
    float* __restrict__ obar)
{
    __shared__ float Qs[64][33];
    __shared__ float Ks[64][33];
    __shared__ float Vt[32][68];   // d-major V tile (float4 over j)
    __shared__ float Ps[64][68];   // probs tile (float4 over j)

    const int qt = blockIdx.x;           // q tile 0..7
    const int bh = blockIdx.y;           // 0..63
    const int b = bh >> 3, h = bh & 7;
    const int q0 = qt << 6;
    const int tid = threadIdx.x;
    const int tx = tid & 15, ty = tid >> 4;

    float cw1r[8], cb1r[8], cw2r[8];
    #pragma unroll
    for (int t = 0; t < 8; t++) {
        cw1r[t] = cw1[t]; cb1r[t] = cb1[t]; cw2r[t] = cw2[h*8 + t];
    }
    const float cb2h = cb2[h];

    const size_t headbase = ((size_t)(b*Hh + h)) * Nseq * DKd;

    // Q tile (contiguous 2048 floats)
    const float* Qb = Q + headbase + (size_t)q0 * DKd;
    for (int t = tid; t < 64*32; t += 256) Qs[t >> 5][t & 31] = Qb[t];

    float o[3][4][2] = {};
    float lsum[3][4] = {};
    const float bars[3] = {0.3f, 0.7f, 1e10f};

    for (int kt = 0; kt < 8; kt++) {
        const int k0 = kt << 6;
        const float* Kb = K + headbase + (size_t)k0 * DKd;
        const float* Vb = V + headbase + (size_t)k0 * DKd;
        for (int t = tid; t < 64*32; t += 256) {
            Ks[t >> 5][t & 31] = Kb[t];
            Vt[t & 31][t >> 5] = Vb[t];
        }
        __syncthreads();

        // ---- S = Q Kt^T (4x4 per thread) ----
        float s[4][4] = {};
        #pragma unroll 8
        for (int d = 0; d < 32; d++) {
            float a[4], kv[4];
            #pragma unroll
            for (int i = 0; i < 4; i++) a[i] = Qs[ty*4 + i][d];
            #pragma unroll
            for (int j = 0; j < 4; j++) kv[j] = Ks[tx*4 + j][d];
            #pragma unroll
            for (int i = 0; i < 4; i++)
                #pragma unroll
                for (int j = 0; j < 4; j++)
                    s[i][j] = fmaf(a[i], kv[j], s[i][j]);
        }

        // ---- dist conv + mask -> e (exp computed ONCE, shared by 3 bars) ----
        float e[4][4], dd[4][4];
        #pragma unroll
        for (int i = 0; i < 4; i++) {
            int qi = q0 + ty*4 + i;
            const float* drow = dist + ((size_t)b*Nseq + qi) * Nseq + k0;
            const int*   mrow = (const int*)mask + ((size_t)b*Nseq + qi) * Nseq + k0;
            float4 d4 = *(const float4*)&drow[tx << 2];
            int4   m4 = *(const int4*)&mrow[tx << 2];
            float dv[4] = {d4.x, d4.y, d4.z, d4.w};
            int   mv[4] = {m4.x, m4.y, m4.z, m4.w};
            #pragma unroll
            for (int j = 0; j < 4; j++) {
                int kj = k0 + tx*4 + j;
                float d = dv[j];
                float conv = cb2h;
                #pragma unroll
                for (int t = 0; t < 8; t++)
                    conv += cw2r[t] * fmaxf(fmaf(d, cw1r[t], cb1r[t]), 0.f);
                float sv = s[i][j] * SCALE * conv;
                e[i][j] = (mv[j] == 0) ? 0.f : __expf(sv);
                // forced-true rows/cols: encode as dist=-1 so (dd < bar) always holds
                dd[i][j] = (qi == 0 || kj == 0) ? -1.f : d;
            }
        }

        // ---- per bar: zero out-of-range e, accumulate l and PV ----
        #pragma unroll
        for (int bar = 0; bar < 3; bar++) {
            const float bv = bars[bar];
            #pragma unroll
            for (int i = 0; i < 4; i++) {
                float p0 = (dd[i][0] < bv) ? e[i][0] : 0.f;
                float p1 = (dd[i][1] < bv) ? e[i][1] : 0.f;
                float p2 = (dd[i][2] < bv) ? e[i][2] : 0.f;
                float p3 = (dd[i][3] < bv) ? e[i][3] : 0.f;
                lsum[bar][i] += (p0 + p1) + (p2 + p3);
                float4 pv = make_float4(p0, p1, p2, p3);
                *(float4*)&Ps[ty*4 + i][tx << 2] = pv;
            }
            __syncthreads();

            const int d0 = tx << 1;
            #pragma unroll
            for (int jg = 0; jg < 16; jg++) {
                float4 v0 = *(const float4*)&Vt[d0][jg << 2];
                float4 v1 = *(const float4*)&Vt[d0 + 1][jg << 2];
                #pragma unroll
                for (int i = 0; i < 4; i++) {
                    float4 p4 = *(const float4*)&Ps[ty*4 + i][jg << 2];
                    o[bar][i][0] += p4.x*v0.x + p4.y*v0.y + p4.z*v0.z + p4.w*v0.w;
                    o[bar][i][1] += p4.x*v1.x + p4.y*v1.y + p4.z*v1.z + p4.w*v1.w;
                }
            }
            __syncthreads();
        }
    }

    // ---- reduce row sums over the 16 lanes owning each row ----
    #pragma unroll
    for (int bar = 0; bar < 3; bar++)
        #pragma unroll
        for (int i = 0; i < 4; i++) {
            float v = lsum[bar][i];
            #pragma unroll
            for (int off = 1; off < 16; off <<= 1)
                v += __shfl_xor_sync(0xffffffffu, v, off);
            lsum[bar][i] = v;
        }

    // ---- normalize + write (bar,B,N,E) ----
    #pragma unroll
    for (int bar = 0; bar < 3; bar++)
        #pragma unroll
        for (int i = 0; i < 4; i++) {
            int qi = q0 + ty*4 + i;
            float rl = 1.f / lsum[bar][i];
            size_t base = ((size_t)bar * Bq * Nseq + (size_t)b * Nseq + qi) * Edim
                        + h * DKd + (tx << 1);
            obar[base]     = o[bar][i][0] * rl;
            obar[base + 1] = o[bar][i][1] * rl;
        }
}

// ---------------- host launcher ----------------------------------------------
extern "C" void kernel_launch(void* const* d_in, const int* in_sizes, int n_in,
                              void* d_out, int out_size)
{
    const float* query = (const float*)d_in[0];
    const float* key   = (const float*)d_in[1];
    const float* value = (const float*)d_in[2];
    const float* dist  = (const float*)d_in[3];
    const int*   mask  = (const int*)d_in[4];
    const float* Wq = (const float*)d_in[5];
    const float* bq = (const float*)d_in[6];
    const float* Wk = (const float*)d_in[7];
    const float* bk = (const float*)d_in[8];
    const float* Wv = (const float*)d_in[9];
    const float* bv = (const float*)d_in[10];
    const float* Wo = (const float*)d_in[11];
    const float* bo = (const float*)d_in[12];
    const float* cw1 = (const float*)d_in[13];
    const float* cb1 = (const float*)d_in[14];
    const float* cw2 = (const float*)d_in[15];
    const float* cb2 = (const float*)d_in[16];
    const float* Ws1 = (const float*)d_in[17];
    const float* bs1 = (const float*)d_in[18];
    const float* Ws2 = (const float*)d_in[19];
    const float* bs2 = (const float*)d_in[20];
    float* out = (float*)d_out;

    float *q_p, *k_p, *v_p, *ob_p, *x_p, *h1_p;
    cudaGetSymbolAddress((void**)&q_p,  g_q);
    cudaGetSymbolAddress((void**)&k_p,  g_k);
    cudaGetSymbolAddress((void**)&v_p,  g_v);
    cudaGetSymbolAddress((void**)&ob_p, g_obar);
    cudaGetSymbolAddress((void**)&x_p,  g_x);
    cudaGetSymbolAddress((void**)&h1_p, g_h1);

    const int M = Bq * Nseq;          // 4096
    dim3 blk(256);

    // QKV projections -> (B,H,N,DK)
    {
        dim3 grid(M / 64, Edim / 64);
        gemm_kernel<<<grid, blk>>>(query, Wq, bq, q_p, M, Edim, Edim, 0, 0, 1);
        gemm_kernel<<<grid, blk>>>(key,   Wk, bk, k_p, M, Edim, Edim, 0, 0, 1);
        gemm_kernel<<<grid, blk>>>(value, Wv, bv, v_p, M, Edim, Edim, 0, 0, 1);
    }

    // fused multi-bar attention
    {
        dim3 grid(Nseq / 64, Bq * Hh);
        attn_kernel<<<grid, blk>>>(q_p, k_p, v_p, dist, mask,
                                   cw1, cb1, cw2, cb2, ob_p);
    }

    // per-bar output projection, written into concat buffer columns
    {
        dim3 grid(M / 64, Edim / 64);
        for (int bar = 0; bar < 3; bar++) {
            gemm_kernel<<<grid, blk>>>(ob_p + (size_t)bar * M * Edim, Wo, bo,
                                       x_p + bar * Edim,
                                       M, Edim, Edim, 3 * Edim, 0, 0);
        }
    }

    // h1 = relu(x @ Ws1 + bs1)
    {
        dim3 grid(M / 64, Edim / 64);
        gemm_kernel<<<grid, blk>>>(x_p, Ws1, bs1, h1_p, M, 3 * Edim, Edim, Edim, 1, 0);
    }

    // out = h1 @ Ws2 + bs2
    {
        dim3 grid(M / 64, Edim / 64);
        gemm_kernel<<<grid, blk>>>(h1_p, Ws2, bs2, out, M, Edim, Edim, Edim, 0, 0);
    }
}

// round 2
// speedup vs baseline: 1.0992x; 1.0992x over previous
#include <cuda_runtime.h>
#include <math.h>

#define Bq   8
#define Nseq 512
#define Edim 256
#define Hh   8
#define DKd  32
#define SCALE 0.17677669529663687f   // 1/sqrt(32)

// ---------------- scratch (device globals; no allocs allowed) ----------------
__device__ float g_q[Bq*Hh*Nseq*DKd];        // (B,H,N,DK)
__device__ float g_k[Bq*Hh*Nseq*DKd];
__device__ float g_v[Bq*Hh*Nseq*DKd];
__device__ float g_obar[3*Bq*Nseq*Edim];     // per-bar attention outputs, (bar,B,N,E)
__device__ float g_x[Bq*Nseq*3*Edim];        // concat buffer (B,N,768)
__device__ float g_h1[Bq*Nseq*Edim];         // relu(x@Ws1+bs1)

// ---------------- 128x64-tile fp32 GEMM, z-batched ---------------------------
// C = act(A@W + bias). blockIdx.z selects among up to 3 (A,W,bias,C) sets.
// headsplit: write C[((b*H+h)*N+n)*DK+d] (for QKV).
__global__ __launch_bounds__(256) void gemm128(
    const float* __restrict__ A0, const float* __restrict__ A1, const float* __restrict__ A2,
    const float* __restrict__ W0, const float* __restrict__ W1, const float* __restrict__ W2,
    const float* __restrict__ bias0, const float* __restrict__ bias1, const float* __restrict__ bias2,
    float* __restrict__ C0, float* __restrict__ C1, float* __restrict__ C2,
    int Kd, int ldw, int ldc, int do_relu, int headsplit)
{
    const int z = blockIdx.z;
    const float* A    = (z == 0) ? A0 : (z == 1) ? A1 : A2;
    const float* W    = (z == 0) ? W0 : (z == 1) ? W1 : W2;
    const float* bias = (z == 0) ? bias0 : (z == 1) ? bias1 : bias2;
    float*       C    = (z == 0) ? C0 : (z == 1) ? C1 : C2;

    __shared__ float As[16][136];   // k-major A tile: As[k][m], m 0..127
    __shared__ float Ws[16][68];    // 16x64 W tile

    const int m0 = blockIdx.x << 7;
    const int n0 = blockIdx.y << 6;
    const int tid = threadIdx.x;
    const int tx = tid & 15, ty = tid >> 4;

    float acc[8][4] = {};

    for (int k0 = 0; k0 < Kd; k0 += 16) {
        {   // A tile: 128x16; thread loads 8 floats of one row, stores transposed
            int r = tid >> 1;
            int c = (tid & 1) << 3;
            const float* ap = &A[(size_t)(m0 + r) * Kd + k0 + c];
            float4 a0 = *(const float4*)ap;
            float4 a1 = *(const float4*)(ap + 4);
            As[c + 0][r] = a0.x; As[c + 1][r] = a0.y;
            As[c + 2][r] = a0.z; As[c + 3][r] = a0.w;
            As[c + 4][r] = a1.x; As[c + 5][r] = a1.y;
            As[c + 6][r] = a1.z; As[c + 7][r] = a1.w;
        }
        {   // W tile
            int r = tid >> 4;
            int c = (tid & 15) << 2;
            *(float4*)&Ws[r][c] = *(const float4*)&W[(size_t)(k0 + r) * ldw + n0 + c];
        }
        __syncthreads();

        #pragma unroll
        for (int kk = 0; kk < 16; kk++) {
            float4 aA = *(const float4*)&As[kk][ty << 3];
            float4 aB = *(const float4*)&As[kk][(ty << 3) + 4];
            float4 w4 = *(const float4*)&Ws[kk][tx << 2];
            float a[8] = {aA.x, aA.y, aA.z, aA.w, aB.x, aB.y, aB.z, aB.w};
            float w[4] = {w4.x, w4.y, w4.z, w4.w};
            #pragma unroll
            for (int i = 0; i < 8; i++)
                #pragma unroll
                for (int j = 0; j < 4; j++)
                    acc[i][j] = fmaf(a[i], w[j], acc[i][j]);
        }
        __syncthreads();
    }

    const int col0 = n0 + (tx << 2);
    float4 b4 = *(const float4*)&bias[col0];
    #pragma unroll
    for (int i = 0; i < 8; i++) {
        int m = m0 + (ty << 3) + i;
        float4 r;
        r.x = acc[i][0] + b4.x; r.y = acc[i][1] + b4.y;
        r.z = acc[i][2] + b4.z; r.w = acc[i][3] + b4.w;
        if (do_relu) {
            r.x = fmaxf(r.x, 0.f); r.y = fmaxf(r.y, 0.f);
            r.z = fmaxf(r.z, 0.f); r.w = fmaxf(r.w, 0.f);
        }
        if (headsplit) {
            int b = m >> 9, n = m & 511;
            int h = col0 >> 5, d = col0 & 31;
            *(float4*)&C[(((size_t)(b*Hh + h))*Nseq + n)*DKd + d] = r;
        } else {
            *(float4*)&C[(size_t)m * ldc + col0] = r;
        }
    }
}

// ---------------- fused multi-bar attention (single-pass PV) ------------------
// exp computed once per score; region code (1 byte) encodes which bars include
// the element. PV accumulates all 3 bars in ONE sweep over (e, r, V).
__global__ __launch_bounds__(256) void attn_kernel(
    const float* __restrict__ Q, const float* __restrict__ K, const float* __restrict__ V,
    const float* __restrict__ dist, const int* __restrict__ mask,
    const float* __restrict__ cw1, const float* __restrict__ cb1,
    const float* __restrict__ cw2, const float* __restrict__ cb2,
    float* __restrict__ obar)
{
    __shared__ float Qs[64][33];
    __shared__ float Ks[64][33];
    __shared__ float Vt[32][68];            // d-major V tile
    __shared__ float Es[64][68];            // exp(scores), unmasked-by-bar
    __shared__ unsigned char Rs[64][68];    // region: 0 (<0.3 or forced), 1 (<0.7), 2

    const int qt = blockIdx.x;
    const int bh = blockIdx.y;
    const int b = bh >> 3, h = bh & 7;
    const int q0 = qt << 6;
    const int tid = threadIdx.x;
    const int tx = tid & 15, ty = tid >> 4;

    float cw1r[8], cb1r[8], cw2r[8];
    #pragma unroll
    for (int t = 0; t < 8; t++) {
        cw1r[t] = cw1[t]; cb1r[t] = cb1[t]; cw2r[t] = cw2[h*8 + t];
    }
    const float cb2h = cb2[h];

    const size_t headbase = ((size_t)(b*Hh + h)) * Nseq * DKd;

    const float* Qb = Q + headbase + (size_t)q0 * DKd;
    for (int t = tid; t < 64*32; t += 256) Qs[t >> 5][t & 31] = Qb[t];

    float o[3][4][2] = {};
    float lsum[3][4] = {};

    for (int kt = 0; kt < 8; kt++) {
        const int k0 = kt << 6;
        const float* Kb = K + headbase + (size_t)k0 * DKd;
        const float* Vb = V + headbase + (size_t)k0 * DKd;
        __syncthreads();    // prev PV done before overwriting Ks/Vt
        for (int t = tid; t < 64*32; t += 256) {
            Ks[t >> 5][t & 31] = Kb[t];
            Vt[t & 31][t >> 5] = Vb[t];
        }
        __syncthreads();

        // ---- S = Q K^T (4x4 per thread) ----
        float s[4][4] = {};
        #pragma unroll 8
        for (int d = 0; d < 32; d++) {
            float a[4], kv[4];
            #pragma unroll
            for (int i = 0; i < 4; i++) a[i] = Qs[ty*4 + i][d];
            #pragma unroll
            for (int j = 0; j < 4; j++) kv[j] = Ks[tx*4 + j][d];
            #pragma unroll
            for (int i = 0; i < 4; i++)
                #pragma unroll
                for (int j = 0; j < 4; j++)
                    s[i][j] = fmaf(a[i], kv[j], s[i][j]);
        }

        // ---- dist conv + mask -> e, region; accumulate lsum; stage to smem ----
        #pragma unroll
        for (int i = 0; i < 4; i++) {
            int qi = q0 + ty*4 + i;
            const float* drow = dist + ((size_t)b*Nseq + qi) * Nseq + k0;
            const int*   mrow = mask + ((size_t)b*Nseq + qi) * Nseq + k0;
            float4 d4 = *(const float4*)&drow[tx << 2];
            int4   m4 = *(const int4*)&mrow[tx << 2];
            float dv[4] = {d4.x, d4.y, d4.z, d4.w};
            int   mv[4] = {m4.x, m4.y, m4.z, m4.w};
            float e[4];
            unsigned int rcode = 0;
            #pragma unroll
            for (int j = 0; j < 4; j++) {
                int kj = k0 + tx*4 + j;
                float d = dv[j];
                float conv = cb2h;
                #pragma unroll
                for (int t = 0; t < 8; t++)
                    conv += cw2r[t] * fmaxf(fmaf(d, cw1r[t], cb1r[t]), 0.f);
                float sv = s[i][j] * SCALE * conv;
                float ev = (mv[j] == 0) ? 0.f : __expf(sv);
                e[j] = ev;
                unsigned int r = (qi == 0 || kj == 0) ? 0u
                               : (d < 0.3f) ? 0u : (d < 0.7f) ? 1u : 2u;
                rcode |= r << (j * 8);
                lsum[2][i] += ev;
                lsum[1][i] += (r < 2u) ? ev : 0.f;
                lsum[0][i] += (r < 1u) ? ev : 0.f;
            }
            *(float4*)&Es[ty*4 + i][tx << 2] = make_float4(e[0], e[1], e[2], e[3]);
            *(unsigned int*)&Rs[ty*4 + i][tx << 2] = rcode;
        }
        __syncthreads();

        // ---- single-pass PV over all 3 bars ----
        const int d0 = tx << 1;
        #pragma unroll
        for (int jg = 0; jg < 16; jg++) {
            float4 v0 = *(const float4*)&Vt[d0][jg << 2];
            float4 v1 = *(const float4*)&Vt[d0 + 1][jg << 2];
            float vv0[4] = {v0.x, v0.y, v0.z, v0.w};
            float vv1[4] = {v1.x, v1.y, v1.z, v1.w};
            #pragma unroll
            for (int i = 0; i < 4; i++) {
                float4 e4 = *(const float4*)&Es[ty*4 + i][jg << 2];
                unsigned int ru = *(const unsigned int*)&Rs[ty*4 + i][jg << 2];
                float ev[4] = {e4.x, e4.y, e4.z, e4.w};
                #pragma unroll
                for (int j = 0; j < 4; j++) {
                    unsigned int r = (ru >> (j * 8)) & 0xffu;
                    float p2 = ev[j];
                    float p1 = (r < 2u) ? p2 : 0.f;
                    float p0 = (r < 1u) ? p2 : 0.f;
                    o[2][i][0] = fmaf(p2, vv0[j], o[2][i][0]);
                    o[2][i][1] = fmaf(p2, vv1[j], o[2][i][1]);
                    o[1][i][0] = fmaf(p1, vv0[j], o[1][i][0]);
                    o[1][i][1] = fmaf(p1, vv1[j], o[1][i][1]);
                    o[0][i][0] = fmaf(p0, vv0[j], o[0][i][0]);
                    o[0][i][1] = fmaf(p0, vv1[j], o[0][i][1]);
                }
            }
        }
    }

    // ---- reduce row sums over the 16 lanes owning each row ----
    #pragma unroll
    for (int bar = 0; bar < 3; bar++)
        #pragma unroll
        for (int i = 0; i < 4; i++) {
            float v = lsum[bar][i];
            #pragma unroll
            for (int off = 1; off < 16; off <<= 1)
                v += __shfl_xor_sync(0xffffffffu, v, off);
            lsum[bar][i] = v;
        }

    // ---- normalize + write (bar,B,N,E) ----
    #pragma unroll
    for (int bar = 0; bar < 3; bar++)
        #pragma unroll
        for (int i = 0; i < 4; i++) {
            int qi = q0 + ty*4 + i;
            float rl = 1.f / lsum[bar][i];
            size_t base = ((size_t)bar * Bq * Nseq + (size_t)b * Nseq + qi) * Edim
                        + h * DKd + (tx << 1);
            obar[base]     = o[bar][i][0] * rl;
            obar[base + 1] = o[bar][i][1] * rl;
        }
}

// ---------------- host launcher ----------------------------------------------
extern "C" void kernel_launch(void* const* d_in, const int* in_sizes, int n_in,
                              void* d_out, int out_size)
{
    const float* query = (const float*)d_in[0];
    const float* key   = (const float*)d_in[1];
    const float* value = (const float*)d_in[2];
    const float* dist  = (const float*)d_in[3];
    const int*   mask  = (const int*)d_in[4];
    const float* Wq = (const float*)d_in[5];
    const float* bq = (const float*)d_in[6];
    const float* Wk = (const float*)d_in[7];
    const float* bk = (const float*)d_in[8];
    const float* Wv = (const float*)d_in[9];
    const float* bv = (const float*)d_in[10];
    const float* Wo = (const float*)d_in[11];
    const float* bo = (const float*)d_in[12];
    const float* cw1 = (const float*)d_in[13];
    const float* cb1 = (const float*)d_in[14];
    const float* cw2 = (const float*)d_in[15];
    const float* cb2 = (const float*)d_in[16];
    const float* Ws1 = (const float*)d_in[17];
    const float* bs1 = (const float*)d_in[18];
    const float* Ws2 = (const float*)d_in[19];
    const float* bs2 = (const float*)d_in[20];
    float* out = (float*)d_out;

    float *q_p, *k_p, *v_p, *ob_p, *x_p, *h1_p;
    cudaGetSymbolAddress((void**)&q_p,  g_q);
    cudaGetSymbolAddress((void**)&k_p,  g_k);
    cudaGetSymbolAddress((void**)&v_p,  g_v);
    cudaGetSymbolAddress((void**)&ob_p, g_obar);
    cudaGetSymbolAddress((void**)&x_p,  g_x);
    cudaGetSymbolAddress((void**)&h1_p, g_h1);

    const int M = Bq * Nseq;          // 4096
    dim3 blk(256);

    // QKV projections -> (B,H,N,DK), batched in z
    {
        dim3 grid(M / 128, Edim / 64, 3);
        gemm128<<<grid, blk>>>(query, key, value,
                               Wq, Wk, Wv,
                               bq, bk, bv,
                               q_p, k_p, v_p,
                               Edim, Edim, 0, 0, 1);
    }

    // fused multi-bar attention
    {
        dim3 grid(Nseq / 64, Bq * Hh);
        attn_kernel<<<grid, blk>>>(q_p, k_p, v_p, dist, mask,
                                   cw1, cb1, cw2, cb2, ob_p);
    }

    // per-bar output projections into concat buffer columns, batched in z
    {
        dim3 grid(M / 128, Edim / 64, 3);
        gemm128<<<grid, blk>>>(ob_p, ob_p + (size_t)M*Edim, ob_p + (size_t)2*M*Edim,
                               Wo, Wo, Wo,
                               bo, bo, bo,
                               x_p, x_p + Edim, x_p + 2*Edim,
                               Edim, Edim, 3*Edim, 0, 0);
    }

    // h1 = relu(x @ Ws1 + bs1)
    {
        dim3 grid(M / 128, Edim / 64, 1);
        gemm128<<<grid, blk>>>(x_p, x_p, x_p, Ws1, Ws1, Ws1, bs1, bs1, bs1,
                               h1_p, h1_p, h1_p, 3*Edim, Edim, Edim, 1, 0);
    }

    // out = h1 @ Ws2 + bs2
    {
        dim3 grid(M / 128, Edim / 64, 1);
        gemm128<<<grid, blk>>>(h1_p, h1_p, h1_p, Ws2, Ws2, Ws2, bs2, bs2, bs2,
                               out, out, out, Edim, Edim, Edim, 0, 0);
    }
}